// round 1
// baseline (speedup 1.0000x reference)
#include <cuda_runtime.h>
#include <math.h>

// ---------------------------------------------------------------------------
// Fused GRU actor-critic forward.
// One CTA (256 threads) processes a 128-sample batch tile entirely in shared
// memory: conv1+pool -> conv2 -> conv3 -> 4 GRU cells -> actor/critic heads.
// Weights are staged stage-by-stage into a reused smem buffer (hot in L2).
// ---------------------------------------------------------------------------

#define NT   256           // threads per CTA
#define TB   128           // batch rows per CTA
#define AST  65            // activation row stride (64 + 1 pad)
#define WST  193           // transposed-weight row stride (192 + 1 pad)
#define GHST 196           // gate buffer row stride (192 + 4 pad)

// smem arena layout (floats). Total 54592 floats = 218368 bytes.
#define O_ACT0  0          // [128][65]   activation ping
#define O_ACT1  8320       // [128][65]   activation pong
#define O_WT    16640      // [64][193]   transposed weight tile
#define O_BIAS  28992      // 512         biases / small head weights
#define O_GH    29504      // [128][196]  gate buffer
#define SMEM_FLOATS 54592
#define SMEM_BYTES  (SMEM_FLOATS * 4)

// conv-phase overlays (temporal reuse of the same arena)
#define O_OBS   0          // [128][149]  staged obs  (dead after conv1)
#define O_CW    19072      // 10544       conv weights+biases
#define O_PB    29616      // [128][145]  pooled conv1 output
#define O_Y2    0          // [128][130]  conv2 output (reuses obs region)
#define O_XT    29616      // [128][65]   conv3 output staging

struct KParams {
    const float* obs;   // [B,7,7,3]
    const float* mem;   // [B,256]
    const float* cw1; const float* cb1;
    const float* cw2; const float* cb2;
    const float* cw3; const float* cb3;
    const float* wih[4]; const float* whh[4];
    const float* bih[4]; const float* bhh[4];
    const float* aw1; const float* ab1; const float* aw2; const float* ab2;
    const float* vw1; const float* vb1; const float* vw2; const float* vb2;
    float* out;
    int B;
};

__device__ __forceinline__ float sigf(float x) {
    return __fdividef(1.0f, 1.0f + __expf(-x));
}
__device__ __forceinline__ float tanh_fast(float x) {
    // tanh(x) = 1 - 2/(e^{2x}+1)   (2 MUFU ops, ~1e-6 abs err)
    return 1.0f - __fdividef(2.0f, __expf(2.0f * x) + 1.0f);
}

// Register-tiled GEMM: each thread computes an 8 x NC tile of
// C[m][u] = bias[u] + sum_k A[m][k] * WT[k][u],  m in [ty*8, ty*8+8),
// u in [ubase, ubase+NC).  A is smem [128][AST], WT is smem [64][WST].
template<int NC>
__device__ __forceinline__ void gemm8xN(const float* __restrict__ A,
                                        const float* __restrict__ WT,
                                        const float* __restrict__ BIAS,
                                        int ty, int ubase, float (&acc)[8][NC])
{
#pragma unroll
    for (int i = 0; i < 8; i++)
#pragma unroll
        for (int j = 0; j < NC; j++) acc[i][j] = BIAS[ubase + j];

    const float* Ab = A + ty * 8 * AST;
#pragma unroll 2
    for (int k = 0; k < 64; k++) {
        float a[8], b[NC];
#pragma unroll
        for (int i = 0; i < 8; i++) a[i] = Ab[i * AST + k];
#pragma unroll
        for (int j = 0; j < NC; j++) b[j] = WT[k * WST + ubase + j];
#pragma unroll
        for (int i = 0; i < 8; i++)
#pragma unroll
            for (int j = 0; j < NC; j++) acc[i][j] = fmaf(a[i], b[j], acc[i][j]);
    }
}

// Load 64 columns of the 256-wide memory matrix into an activation buffer.
__device__ __forceinline__ void load_h(float* dst, const float* mem,
                                       int r0, int off, int tid)
{
    for (int idx = tid; idx < TB * 16; idx += NT) {
        int m = idx >> 4, q = idx & 15;
        const float4 v = *reinterpret_cast<const float4*>(
            mem + (size_t)(r0 + m) * 256 + off + q * 4);
        float* d = dst + m * AST + q * 4;
        d[0] = v.x; d[1] = v.y; d[2] = v.z; d[3] = v.w;
    }
}

// One GRU cell.  AX = input x (read), AH = hidden h (read, then overwritten
// with h').  h' is also streamed to global memory_out (row stride 256).
__device__ void gru_cell(const float* AX, float* AH,
                         const float* __restrict__ wih, const float* __restrict__ whh,
                         const float* __restrict__ bih, const float* __restrict__ bhh,
                         float* WT, float* BIAS, float* GH,
                         float* __restrict__ moutg, int tid)
{
    // stage whh^T (WT[k][u] = whh[u][k]) and both bias vectors
    for (int idx = tid; idx < 192 * 64; idx += NT) {
        int u = idx >> 6, k = idx & 63;
        WT[k * WST + u] = whh[idx];
    }
    for (int i = tid; i < 192; i += NT) { BIAS[i] = bih[i]; BIAS[192 + i] = bhh[i]; }
    __syncthreads();

    const int ty = tid >> 4, tx = tid & 15;

    // pass 1: gh = h @ whh^T + bhh   (all 192 columns)
    {
        float acc[8][12];
        gemm8xN<12>(AH, WT, BIAS + 192, ty, tx * 12, acc);
#pragma unroll
        for (int i = 0; i < 8; i++)
#pragma unroll
            for (int j = 0; j < 12; j++)
                GH[(ty * 8 + i) * GHST + tx * 12 + j] = acc[i][j];
    }
    __syncthreads();

    // stage wih^T
    for (int idx = tid; idx < 192 * 64; idx += NT) {
        int u = idx >> 6, k = idx & 63;
        WT[k * WST + u] = wih[idx];
    }
    __syncthreads();

    // pass 2a: columns 0..127 -> r, z = sigmoid(gi + gh), stored in place
    {
        float acc[8][8];
        gemm8xN<8>(AX, WT, BIAS, ty, tx * 8, acc);
#pragma unroll
        for (int i = 0; i < 8; i++)
#pragma unroll
            for (int j = 0; j < 8; j++) {
                int m = ty * 8 + i, u = tx * 8 + j;
                GH[m * GHST + u] = sigf(acc[i][j] + GH[m * GHST + u]);
            }
    }
    __syncthreads();

    // pass 2b: columns 128..191 -> n gate, combine, write h'
    {
        float acc[8][4];
        gemm8xN<4>(AX, WT, BIAS, ty, 128 + tx * 4, acc);
#pragma unroll
        for (int i = 0; i < 8; i++) {
            int m = ty * 8 + i;
            float hv[4];
#pragma unroll
            for (int j = 0; j < 4; j++) {
                int un = tx * 4 + j;
                float r  = GH[m * GHST + un];
                float z  = GH[m * GHST + 64 + un];
                float hn = GH[m * GHST + 128 + un];
                float n  = tanh_fast(acc[i][j] + r * hn);
                float h  = AH[m * AST + un];
                float hp = n + z * (h - n);        // (1-z)*n + z*h
                AH[m * AST + un] = hp;
                hv[j] = hp;
            }
            *reinterpret_cast<float4*>(moutg + (size_t)m * 256 + tx * 4) =
                make_float4(hv[0], hv[1], hv[2], hv[3]);
        }
    }
    __syncthreads();
}

__global__ void __launch_bounds__(NT, 1) fused_kernel(KParams P)
{
    extern __shared__ float S[];
    const int tid = threadIdx.x;
    const int r0  = blockIdx.x * TB;
    const int B   = P.B;

    // =================== conv phase ===================
    float* OBSB = S + O_OBS;
    float* CW   = S + O_CW;
    float* PB   = S + O_PB;
    float* Y2   = S + O_Y2;
    float* XT   = S + O_XT;

    // stage conv weights:  w1[0:192) b1[192:208) w2[208:2256) b2[2256:2288)
    //                      w3[2288:10480) b3[10480:10544)
    for (int i = tid; i < 192;  i += NT) CW[i]         = P.cw1[i];
    for (int i = tid; i < 16;   i += NT) CW[192 + i]   = P.cb1[i];
    for (int i = tid; i < 2048; i += NT) CW[208 + i]   = P.cw2[i];
    for (int i = tid; i < 32;   i += NT) CW[2256 + i]  = P.cb2[i];
    for (int i = tid; i < 8192; i += NT) CW[2288 + i]  = P.cw3[i];
    for (int i = tid; i < 64;   i += NT) CW[10480 + i] = P.cb3[i];

    // stage obs tile (NHWC, 147 floats / sample, padded row stride 149)
    for (int idx = tid; idx < TB * 147; idx += NT) {
        int m = idx / 147, e = idx - m * 147;
        OBSB[m * 149 + e] = P.obs[(size_t)(r0 + m) * 147 + e];
    }
    __syncthreads();

    const int s = tid & 127, half = tid >> 7;   // 2 threads per sample

    // conv1 (3->16ch, 2x2, valid) + relu + 2x2 maxpool (relu after max: same)
    {
        const float* ob = OBSB + s * 149;
        float w1r[8][12], b1r[8];
#pragma unroll
        for (int c = 0; c < 8; c++) {
            b1r[c] = CW[192 + half * 8 + c];
#pragma unroll
            for (int q = 0; q < 12; q++) w1r[c][q] = CW[(half * 8 + c) * 12 + q];
        }
#pragma unroll
        for (int a = 0; a < 3; a++)
#pragma unroll
        for (int b = 0; b < 3; b++) {
            float vmax[8];
#pragma unroll
            for (int c = 0; c < 8; c++) vmax[c] = -1e30f;
#pragma unroll
            for (int di = 0; di < 2; di++)
#pragma unroll
            for (int dj = 0; dj < 2; dj++) {
                int i = 2 * a + di, j = 2 * b + dj;
                float o[12];
#pragma unroll
                for (int kh = 0; kh < 2; kh++)
#pragma unroll
                for (int kw = 0; kw < 2; kw++)
#pragma unroll
                for (int c3 = 0; c3 < 3; c3++)
                    o[c3 * 4 + kh * 2 + kw] = ob[(i + kh) * 21 + (j + kw) * 3 + c3];
#pragma unroll
                for (int c = 0; c < 8; c++) {
                    float v = b1r[c];
#pragma unroll
                    for (int q = 0; q < 12; q++) v = fmaf(o[q], w1r[c][q], v);
                    vmax[c] = fmaxf(vmax[c], v);
                }
            }
#pragma unroll
            for (int c = 0; c < 8; c++)
                PB[s * 145 + (half * 8 + c) * 9 + a * 3 + b] = fmaxf(vmax[c], 0.0f);
        }
    }
    __syncthreads();   // p complete (both halves); obs region now reusable

    // conv2 (16->32ch, 2x2 on 3x3 -> 2x2) + relu
    {
#pragma unroll
        for (int pi = 0; pi < 2; pi++)
#pragma unroll
        for (int pj = 0; pj < 2; pj++) {
            float pv[64];
#pragma unroll
            for (int c1 = 0; c1 < 16; c1++)
#pragma unroll
            for (int kh = 0; kh < 2; kh++)
#pragma unroll
            for (int kw = 0; kw < 2; kw++)
                pv[c1 * 4 + kh * 2 + kw] =
                    PB[s * 145 + c1 * 9 + (pi + kh) * 3 + (pj + kw)];
            for (int c2l = 0; c2l < 16; c2l++) {
                int c2 = half * 16 + c2l;
                float v = CW[2256 + c2];
                const float* w = CW + 208 + c2 * 64;
#pragma unroll
                for (int t = 0; t < 64; t++) v = fmaf(pv[t], w[t], v);
                Y2[s * 130 + c2 * 4 + pi * 2 + pj] = fmaxf(v, 0.0f);
            }
        }
    }
    __syncthreads();   // y2 complete (cross-half dependency in conv3)

    // conv3 (32->64ch, 2x2 on 2x2 -> 1x1) + relu
    {
        float acc3[32];
#pragma unroll
        for (int o = 0; o < 32; o++) acc3[o] = CW[10480 + half * 32 + o];
#pragma unroll
        for (int ch = 0; ch < 4; ch++) {
            float yv[32];
#pragma unroll
            for (int q = 0; q < 32; q++) yv[q] = Y2[s * 130 + ch * 32 + q];
            for (int o = 0; o < 32; o++) {
                const float* w = CW + 2288 + (half * 32 + o) * 128 + ch * 32;
#pragma unroll
                for (int q = 0; q < 32; q++) acc3[o] = fmaf(yv[q], w[q], acc3[o]);
            }
        }
#pragma unroll
        for (int o = 0; o < 32; o++)
            XT[s * 65 + half * 32 + o] = fmaxf(acc3[o], 0.0f);
    }
    __syncthreads();

    // =================== GRU phase ===================
    float* A0   = S + O_ACT0;
    float* A1   = S + O_ACT1;
    float* WT   = S + O_WT;
    float* BIAS = S + O_BIAS;
    float* GH   = S + O_GH;

    // move conv output into ACT0 (XT overlaps GH region)
    for (int i = tid; i < TB * AST; i += NT) A0[i] = XT[i];
    __syncthreads();

    float* moutg = P.out + (size_t)4 * B + (size_t)r0 * 256;

    load_h(A1, P.mem, r0, 0, tid);
    __syncthreads();
    gru_cell(A0, A1, P.wih[0], P.whh[0], P.bih[0], P.bhh[0],
             WT, BIAS, GH, moutg + 0, tid);          // h1_0 -> A1

    load_h(A0, P.mem, r0, 64, tid);
    __syncthreads();
    gru_cell(A1, A0, P.wih[1], P.whh[1], P.bih[1], P.bhh[1],
             WT, BIAS, GH, moutg + 64, tid);         // h1_1 -> A0

    load_h(A1, P.mem, r0, 128, tid);
    __syncthreads();
    gru_cell(A0, A1, P.wih[2], P.whh[2], P.bih[2], P.bhh[2],
             WT, BIAS, GH, moutg + 128, tid);        // h2_0 -> A1

    load_h(A0, P.mem, r0, 192, tid);
    __syncthreads();
    gru_cell(A1, A0, P.wih[3], P.whh[3], P.bih[3], P.bhh[3],
             WT, BIAS, GH, moutg + 192, tid);        // h2_1 (embedding) -> A0

    // =================== heads ===================
    // stack actor_w1 (cols 0..63) and critic_w1 (cols 64..127) -> one GEMM
    for (int idx = tid; idx < 64 * 64; idx += NT) {
        int u = idx >> 6, k = idx & 63;
        WT[k * WST + u] = P.aw1[idx];
    }
    for (int idx = tid; idx < 64 * 64; idx += NT) {
        int u = idx >> 6, k = idx & 63;
        WT[k * WST + 64 + u] = P.vw1[idx];
    }
    for (int i = tid; i < 64; i += NT) { BIAS[i] = P.ab1[i]; BIAS[64 + i] = P.vb1[i]; }
    for (int i = tid; i < 192; i += NT) BIAS[128 + i] = P.aw2[i];
    for (int i = tid; i < 3;   i += NT) BIAS[320 + i] = P.ab2[i];
    for (int i = tid; i < 64;  i += NT) BIAS[336 + i] = P.vw2[i];
    if (tid == 0) BIAS[400] = P.vb2[0];
    __syncthreads();

    {
        const int ty = tid >> 4, tx = tid & 15;
        float acc[8][8];
        gemm8xN<8>(A0, WT, BIAS, ty, tx * 8, acc);
#pragma unroll
        for (int i = 0; i < 8; i++)
#pragma unroll
            for (int j = 0; j < 8; j++)
                GH[(ty * 8 + i) * 132 + tx * 8 + j] = fmaxf(acc[i][j], 0.0f);
    }
    __syncthreads();

    if (tid < 128) {
        // actor second layer + log_softmax for sample m
        const int m = tid;
        float l0 = BIAS[320], l1 = BIAS[321], l2 = BIAS[322];
        for (int k = 0; k < 64; k++) {
            float a = GH[m * 132 + k];
            l0 = fmaf(a, BIAS[128 + k],        l0);
            l1 = fmaf(a, BIAS[128 + 64 + k],   l1);
            l2 = fmaf(a, BIAS[128 + 128 + k],  l2);
        }
        float mx  = fmaxf(l0, fmaxf(l1, l2));
        float lse = mx + logf(__expf(l0 - mx) + __expf(l1 - mx) + __expf(l2 - mx));
        float* o = P.out + (size_t)(r0 + m) * 3;
        o[0] = l0 - lse; o[1] = l1 - lse; o[2] = l2 - lse;
    } else {
        // critic second layer for sample m
        const int m = tid - 128;
        float v = BIAS[400];
        for (int k = 0; k < 64; k++)
            v = fmaf(GH[m * 132 + 64 + k], BIAS[336 + k], v);
        P.out[(size_t)3 * B + r0 + m] = v;
    }
}

extern "C" void kernel_launch(void* const* d_in, const int* in_sizes, int n_in,
                              void* d_out, int out_size)
{
    KParams P;
    P.obs = (const float*)d_in[0];
    P.mem = (const float*)d_in[1];
    P.cw1 = (const float*)d_in[2];  P.cb1 = (const float*)d_in[3];
    P.cw2 = (const float*)d_in[4];  P.cb2 = (const float*)d_in[5];
    P.cw3 = (const float*)d_in[6];  P.cb3 = (const float*)d_in[7];
    // cells in order: g1 layer0, g1 layer1, g2 layer0, g2 layer1
    for (int c = 0; c < 4; c++) {
        P.wih[c] = (const float*)d_in[8 + c * 4 + 0];
        P.whh[c] = (const float*)d_in[8 + c * 4 + 1];
        P.bih[c] = (const float*)d_in[8 + c * 4 + 2];
        P.bhh[c] = (const float*)d_in[8 + c * 4 + 3];
    }
    P.aw1 = (const float*)d_in[24]; P.ab1 = (const float*)d_in[25];
    P.aw2 = (const float*)d_in[26]; P.ab2 = (const float*)d_in[27];
    P.vw1 = (const float*)d_in[28]; P.vb1 = (const float*)d_in[29];
    P.vw2 = (const float*)d_in[30]; P.vb2 = (const float*)d_in[31];
    P.out = (float*)d_out;
    P.B   = in_sizes[0] / 147;   // obs elements = B*7*7*3

    cudaFuncSetAttribute(fused_kernel,
                         cudaFuncAttributeMaxDynamicSharedMemorySize, SMEM_BYTES);
    fused_kernel<<<P.B / TB, NT, SMEM_BYTES>>>(P);
}

// round 3
// speedup vs baseline: 1.0991x; 1.0991x over previous
#include <cuda_runtime.h>
#include <math.h>

// ---------------------------------------------------------------------------
// Fused GRU actor-critic forward, round 2: packed f32x2 FMA GEMMs,
// merged GRU gate pass, vectorized conv weight loads.
// One CTA (256 threads) owns a 128-sample tile entirely in shared memory.
// ---------------------------------------------------------------------------

#define NT   256           // threads per CTA
#define TB   128           // batch rows per CTA
#define AST  68            // activation row stride (64 + 4 pad, float4-able)
#define WST  196           // transposed-weight row stride (192 + 4 pad)
#define GHST 196           // gate buffer row stride

// smem arena (floats). Total 55552 floats = 222208 bytes.
#define O_ACT0  0          // [128][68]   activation ping
#define O_ACT1  8704       // [128][68]   activation pong
#define O_WT    17408      // [64][196]   transposed weight tile
#define O_BIAS  29952      // 512         biases / small head weights
#define O_GH    30464      // [128][196]  gate buffer
#define SMEM_FLOATS 55552
#define SMEM_BYTES  (SMEM_FLOATS * 4)

// conv-phase overlays (temporal reuse)
#define O_OBS   0          // [128][149]  staged obs (dead after conv1)
#define O_CW    19072      // 10544       conv weights+biases
#define O_PB    29616      // [128][145]  pooled conv1 output
#define O_Y2    0          // [128][132]  conv2 output (reuses obs region)
#define O_XT    29616      // [128][68]   conv3 output staging (PB dead)

typedef unsigned long long u64;

struct KParams {
    const float* obs;
    const float* mem;
    const float* cw1; const float* cb1;
    const float* cw2; const float* cb2;
    const float* cw3; const float* cb3;
    const float* wih[4]; const float* whh[4];
    const float* bih[4]; const float* bhh[4];
    const float* aw1; const float* ab1; const float* aw2; const float* ab2;
    const float* vw1; const float* vb1; const float* vw2; const float* vb2;
    float* out;
    int B;
};

__device__ __forceinline__ float sigf(float x) {
    return __fdividef(1.0f, 1.0f + __expf(-x));
}
__device__ __forceinline__ float tanh_fast(float x) {
    return 1.0f - __fdividef(2.0f, __expf(2.0f * x) + 1.0f);
}

// ---- packed f32x2 helpers -------------------------------------------------
__device__ __forceinline__ u64 splat2(float a) {
    u64 r; unsigned u = __float_as_uint(a);
    asm("mov.b64 %0, {%1, %1};" : "=l"(r) : "r"(u));
    return r;
}
__device__ __forceinline__ void ffma2(u64 &d, u64 a, u64 b) {
    asm("fma.rn.f32x2 %0, %1, %2, %0;" : "+l"(d) : "l"(a), "l"(b));
}
__device__ __forceinline__ float lo2(u64 v) { return __uint_as_float((unsigned)v); }
__device__ __forceinline__ float hi2(u64 v) { return __uint_as_float((unsigned)(v >> 32)); }

// Contiguous-column packed GEMM: thread computes rows [ty*8, ty*8+8) x
// column pairs [ubase, ubase+2*NP).  A smem [128][AST], WT smem [64][WST].
template<int NP>
__device__ __forceinline__ void gemmP(const float* __restrict__ A,
                                      const float* __restrict__ WT,
                                      const float* __restrict__ BIAS,
                                      int ty, int ubase, u64 (&acc)[8][NP])
{
#pragma unroll
    for (int j = 0; j < NP; j++) {
        u64 b0 = *reinterpret_cast<const u64*>(BIAS + ubase + 2 * j);
#pragma unroll
        for (int i = 0; i < 8; i++) acc[i][j] = b0;
    }
    const float* Ab = A + ty * 8 * AST;
#pragma unroll 2
    for (int k = 0; k < 64; k++) {
        u64 ap[8], bv[NP];
#pragma unroll
        for (int i = 0; i < 8; i++) ap[i] = splat2(Ab[i * AST + k]);
#pragma unroll
        for (int j = 0; j < NP; j++)
            bv[j] = *reinterpret_cast<const u64*>(WT + k * WST + ubase + 2 * j);
#pragma unroll
        for (int i = 0; i < 8; i++)
#pragma unroll
            for (int j = 0; j < NP; j++) ffma2(acc[i][j], ap[i], bv[j]);
    }
}

// Load 64 columns of the 256-wide memory matrix into an activation buffer.
__device__ __forceinline__ void load_h(float* dst, const float* mem,
                                       int r0, int off, int tid)
{
    for (int idx = tid; idx < TB * 16; idx += NT) {
        int m = idx >> 4, q = idx & 15;
        const float4 v = *reinterpret_cast<const float4*>(
            mem + (size_t)(r0 + m) * 256 + off + q * 4);
        *reinterpret_cast<float4*>(dst + m * AST + q * 4) = v;
    }
}

// One GRU cell.  AX = input x (read), AH = hidden h (read, overwritten with
// h').  h' also streamed to global memory_out (row stride 256).
__device__ void gru_cell(const float* AX, float* AH,
                         const float* __restrict__ wih, const float* __restrict__ whh,
                         const float* __restrict__ bih, const float* __restrict__ bhh,
                         float* WT, float* BIAS, float* GH,
                         float* __restrict__ moutg, int tid)
{
    // stage whh^T and biases
    for (int idx = tid; idx < 192 * 64; idx += NT) {
        int u = idx >> 6, k = idx & 63;
        WT[k * WST + u] = whh[idx];
    }
    for (int i = tid; i < 192; i += NT) { BIAS[i] = bih[i]; BIAS[192 + i] = bhh[i]; }
    __syncthreads();

    const int ty = tid >> 4, tx = tid & 15;

    // pass 1: gh = h @ whh^T + bhh  (all 192 columns, contiguous 12/thread)
    {
        u64 acc[8][6];
        gemmP<6>(AH, WT, BIAS + 192, ty, tx * 12, acc);
#pragma unroll
        for (int i = 0; i < 8; i++)
#pragma unroll
            for (int j = 0; j < 6; j++)
                *reinterpret_cast<u64*>(GH + (ty * 8 + i) * GHST + tx * 12 + 2 * j)
                    = acc[i][j];
    }
    __syncthreads();

    // stage wih^T
    for (int idx = tid; idx < 192 * 64; idx += NT) {
        int u = idx >> 6, k = idx & 63;
        WT[k * WST + u] = wih[idx];
    }
    __syncthreads();

    // pass 2: gi for gate-matched columns {ub, 64+ub, 128+ub} (4 each),
    // then fully thread-local gate combine.
    {
        const int ub = tx * 4;
        u64 acc[8][6];
#pragma unroll
        for (int g = 0; g < 3; g++)
#pragma unroll
        for (int p = 0; p < 2; p++) {
            u64 b0 = *reinterpret_cast<const u64*>(BIAS + g * 64 + ub + 2 * p);
#pragma unroll
            for (int i = 0; i < 8; i++) acc[i][g * 2 + p] = b0;
        }
        const float* Ab = AX + ty * 8 * AST;
#pragma unroll 2
        for (int k = 0; k < 64; k++) {
            u64 ap[8], bv[6];
#pragma unroll
            for (int i = 0; i < 8; i++) ap[i] = splat2(Ab[i * AST + k]);
#pragma unroll
            for (int g = 0; g < 3; g++)
#pragma unroll
            for (int p = 0; p < 2; p++)
                bv[g * 2 + p] = *reinterpret_cast<const u64*>(
                    WT + k * WST + g * 64 + ub + 2 * p);
#pragma unroll
            for (int i = 0; i < 8; i++)
#pragma unroll
                for (int j = 0; j < 6; j++) ffma2(acc[i][j], ap[i], bv[j]);
        }
#pragma unroll
        for (int i = 0; i < 8; i++) {
            const int m = ty * 8 + i;
            const float4 ghr = *reinterpret_cast<const float4*>(GH + m * GHST + ub);
            const float4 ghz = *reinterpret_cast<const float4*>(GH + m * GHST + 64 + ub);
            const float4 ghn = *reinterpret_cast<const float4*>(GH + m * GHST + 128 + ub);
            const float4 h4  = *reinterpret_cast<const float4*>(AH + m * AST + ub);
            float gr[4] = { lo2(acc[i][0]), hi2(acc[i][0]), lo2(acc[i][1]), hi2(acc[i][1]) };
            float gz[4] = { lo2(acc[i][2]), hi2(acc[i][2]), lo2(acc[i][3]), hi2(acc[i][3]) };
            float gn[4] = { lo2(acc[i][4]), hi2(acc[i][4]), lo2(acc[i][5]), hi2(acc[i][5]) };
            const float hr[4] = { ghr.x, ghr.y, ghr.z, ghr.w };
            const float hz[4] = { ghz.x, ghz.y, ghz.z, ghz.w };
            const float hn[4] = { ghn.x, ghn.y, ghn.z, ghn.w };
            const float ho[4] = { h4.x, h4.y, h4.z, h4.w };
            float hp[4];
#pragma unroll
            for (int c = 0; c < 4; c++) {
                float r = sigf(gr[c] + hr[c]);
                float z = sigf(gz[c] + hz[c]);
                float n = tanh_fast(gn[c] + r * hn[c]);
                hp[c] = n + z * (ho[c] - n);
            }
            const float4 o4 = make_float4(hp[0], hp[1], hp[2], hp[3]);
            *reinterpret_cast<float4*>(AH + m * AST + ub) = o4;
            *reinterpret_cast<float4*>(moutg + (size_t)m * 256 + ub) = o4;
        }
    }
    __syncthreads();
}

__global__ void __launch_bounds__(NT, 1) fused_kernel(KParams P)
{
    extern __shared__ float S[];
    const int tid = threadIdx.x;
    const int r0  = blockIdx.x * TB;
    const int B   = P.B;

    // =================== conv phase ===================
    float* OBSB = S + O_OBS;
    float* CW   = S + O_CW;
    float* PB   = S + O_PB;
    float* Y2   = S + O_Y2;
    float* XT   = S + O_XT;

    // stage conv weights: w1[0:192) b1[192:208) w2[208:2256) b2[2256:2288)
    //                     w3[2288:10480) b3[10480:10544)
    for (int i = tid; i < 192;  i += NT) CW[i]         = P.cw1[i];
    for (int i = tid; i < 16;   i += NT) CW[192 + i]   = P.cb1[i];
    for (int i = tid; i < 2048; i += NT) CW[208 + i]   = P.cw2[i];
    for (int i = tid; i < 32;   i += NT) CW[2256 + i]  = P.cb2[i];
    for (int i = tid; i < 8192; i += NT) CW[2288 + i]  = P.cw3[i];
    for (int i = tid; i < 64;   i += NT) CW[10480 + i] = P.cb3[i];

    // stage obs tile (NHWC, 147 floats / sample, padded row stride 149)
    for (int idx = tid; idx < TB * 147; idx += NT) {
        int m = idx / 147, e = idx - m * 147;
        OBSB[m * 149 + e] = P.obs[(size_t)(r0 + m) * 147 + e];
    }
    __syncthreads();

    const int s = tid & 127, half = tid >> 7;   // 2 threads per sample

    // conv1 (3->16ch, 2x2) + relu + 2x2 maxpool
    {
        const float* ob = OBSB + s * 149;
        float w1r[8][12], b1r[8];
#pragma unroll
        for (int c = 0; c < 8; c++) {
            b1r[c] = CW[192 + half * 8 + c];
#pragma unroll
            for (int q = 0; q < 12; q++) w1r[c][q] = CW[(half * 8 + c) * 12 + q];
        }
#pragma unroll
        for (int a = 0; a < 3; a++)
#pragma unroll
        for (int b = 0; b < 3; b++) {
            float vmax[8];
#pragma unroll
            for (int c = 0; c < 8; c++) vmax[c] = -1e30f;
#pragma unroll
            for (int di = 0; di < 2; di++)
#pragma unroll
            for (int dj = 0; dj < 2; dj++) {
                int i = 2 * a + di, j = 2 * b + dj;
                float o[12];
#pragma unroll
                for (int kh = 0; kh < 2; kh++)
#pragma unroll
                for (int kw = 0; kw < 2; kw++)
#pragma unroll
                for (int c3 = 0; c3 < 3; c3++)
                    o[c3 * 4 + kh * 2 + kw] = ob[(i + kh) * 21 + (j + kw) * 3 + c3];
#pragma unroll
                for (int c = 0; c < 8; c++) {
                    float v = b1r[c];
#pragma unroll
                    for (int q = 0; q < 12; q++) v = fmaf(o[q], w1r[c][q], v);
                    vmax[c] = fmaxf(vmax[c], v);
                }
            }
#pragma unroll
            for (int c = 0; c < 8; c++)
                PB[s * 145 + (half * 8 + c) * 9 + a * 3 + b] = fmaxf(vmax[c], 0.0f);
        }
    }
    __syncthreads();

    // conv2 (16->32ch, 2x2 on 3x3 -> 2x2) + relu, float4 weight loads
    {
#pragma unroll
        for (int pi = 0; pi < 2; pi++)
#pragma unroll
        for (int pj = 0; pj < 2; pj++) {
            float pv[64];
#pragma unroll
            for (int c1 = 0; c1 < 16; c1++)
#pragma unroll
            for (int kh = 0; kh < 2; kh++)
#pragma unroll
            for (int kw = 0; kw < 2; kw++)
                pv[c1 * 4 + kh * 2 + kw] =
                    PB[s * 145 + c1 * 9 + (pi + kh) * 3 + (pj + kw)];
            for (int c2l = 0; c2l < 16; c2l++) {
                int c2 = half * 16 + c2l;
                float v = CW[2256 + c2];
                const float4* w4 = reinterpret_cast<const float4*>(CW + 208 + c2 * 64);
#pragma unroll
                for (int t = 0; t < 16; t++) {
                    float4 w = w4[t];
                    v = fmaf(pv[4 * t + 0], w.x, v);
                    v = fmaf(pv[4 * t + 1], w.y, v);
                    v = fmaf(pv[4 * t + 2], w.z, v);
                    v = fmaf(pv[4 * t + 3], w.w, v);
                }
                Y2[s * 132 + c2 * 4 + pi * 2 + pj] = fmaxf(v, 0.0f);
            }
        }
    }
    __syncthreads();

    // conv3 (32->64ch, 2x2 on 2x2 -> 1x1) + relu, float4 loads both sides
    {
        float acc3[32];
#pragma unroll
        for (int o = 0; o < 32; o++) acc3[o] = CW[10480 + half * 32 + o];
#pragma unroll
        for (int ch = 0; ch < 4; ch++) {
            float4 yv4[8];
#pragma unroll
            for (int q = 0; q < 8; q++)
                yv4[q] = *reinterpret_cast<const float4*>(Y2 + s * 132 + ch * 32 + q * 4);
            for (int o = 0; o < 32; o++) {
                const float4* w4 = reinterpret_cast<const float4*>(
                    CW + 2288 + (half * 32 + o) * 128 + ch * 32);
                float v = acc3[o];
#pragma unroll
                for (int q = 0; q < 8; q++) {
                    float4 w = w4[q];
                    v = fmaf(yv4[q].x, w.x, v);
                    v = fmaf(yv4[q].y, w.y, v);
                    v = fmaf(yv4[q].z, w.z, v);
                    v = fmaf(yv4[q].w, w.w, v);
                }
                acc3[o] = v;
            }
        }
#pragma unroll
        for (int o = 0; o < 32; o++)
            XT[s * AST + half * 32 + o] = fmaxf(acc3[o], 0.0f);
    }
    __syncthreads();

    // =================== GRU phase ===================
    float* A0   = S + O_ACT0;
    float* A1   = S + O_ACT1;
    float* WT   = S + O_WT;
    float* BIAS = S + O_BIAS;
    float* GH   = S + O_GH;

    // move conv output into ACT0 (XT overlaps BIAS/GH region)
    for (int i = tid; i < TB * AST / 4; i += NT)
        reinterpret_cast<float4*>(A0)[i] = reinterpret_cast<const float4*>(XT)[i];
    __syncthreads();

    float* moutg = P.out + (size_t)4 * B + (size_t)r0 * 256;

    load_h(A1, P.mem, r0, 0, tid);
    __syncthreads();
    gru_cell(A0, A1, P.wih[0], P.whh[0], P.bih[0], P.bhh[0],
             WT, BIAS, GH, moutg + 0, tid);          // h1_0 -> A1

    load_h(A0, P.mem, r0, 64, tid);
    __syncthreads();
    gru_cell(A1, A0, P.wih[1], P.whh[1], P.bih[1], P.bhh[1],
             WT, BIAS, GH, moutg + 64, tid);         // h1_1 -> A0

    load_h(A1, P.mem, r0, 128, tid);
    __syncthreads();
    gru_cell(A0, A1, P.wih[2], P.whh[2], P.bih[2], P.bhh[2],
             WT, BIAS, GH, moutg + 128, tid);        // h2_0 -> A1

    load_h(A0, P.mem, r0, 192, tid);
    __syncthreads();
    gru_cell(A1, A0, P.wih[3], P.whh[3], P.bih[3], P.bhh[3],
             WT, BIAS, GH, moutg + 192, tid);        // h2_1 (embedding) -> A0

    // =================== heads ===================
    // stack actor_w1 (cols 0..63) and critic_w1 (cols 64..127) -> one GEMM
    for (int idx = tid; idx < 64 * 64; idx += NT) {
        int u = idx >> 6, k = idx & 63;
        WT[k * WST + u] = P.aw1[idx];
    }
    for (int idx = tid; idx < 64 * 64; idx += NT) {
        int u = idx >> 6, k = idx & 63;
        WT[k * WST + 64 + u] = P.vw1[idx];
    }
    for (int i = tid; i < 64; i += NT) { BIAS[i] = P.ab1[i]; BIAS[64 + i] = P.vb1[i]; }
    for (int i = tid; i < 192; i += NT) BIAS[128 + i] = P.aw2[i];
    for (int i = tid; i < 3;   i += NT) BIAS[320 + i] = P.ab2[i];
    for (int i = tid; i < 64;  i += NT) BIAS[336 + i] = P.vw2[i];
    if (tid == 0) BIAS[400] = P.vb2[0];
    __syncthreads();

    {
        const int ty = tid >> 4, tx = tid & 15;
        u64 acc[8][4];
        gemmP<4>(A0, WT, BIAS, ty, tx * 8, acc);
#pragma unroll
        for (int i = 0; i < 8; i++) {
            float* g = GH + (ty * 8 + i) * 132 + tx * 8;
#pragma unroll
            for (int j = 0; j < 4; j++) {
                g[2 * j + 0] = fmaxf(lo2(acc[i][j]), 0.0f);
                g[2 * j + 1] = fmaxf(hi2(acc[i][j]), 0.0f);
            }
        }
    }
    __syncthreads();

    if (tid < 128) {
        // actor second layer + log_softmax for sample m
        const int m = tid;
        float l0 = BIAS[320], l1 = BIAS[321], l2 = BIAS[322];
        for (int k = 0; k < 64; k++) {
            float a = GH[m * 132 + k];
            l0 = fmaf(a, BIAS[128 + k],       l0);
            l1 = fmaf(a, BIAS[128 + 64 + k],  l1);
            l2 = fmaf(a, BIAS[128 + 128 + k], l2);
        }
        float mx  = fmaxf(l0, fmaxf(l1, l2));
        float lse = mx + logf(__expf(l0 - mx) + __expf(l1 - mx) + __expf(l2 - mx));
        float* o = P.out + (size_t)(r0 + m) * 3;
        o[0] = l0 - lse; o[1] = l1 - lse; o[2] = l2 - lse;
    } else {
        // critic second layer for sample m
        const int m = tid - 128;
        float v = BIAS[400];
        for (int k = 0; k < 64; k++)
            v = fmaf(GH[m * 132 + 64 + k], BIAS[336 + k], v);
        P.out[(size_t)3 * B + r0 + m] = v;
    }
}

extern "C" void kernel_launch(void* const* d_in, const int* in_sizes, int n_in,
                              void* d_out, int out_size)
{
    KParams P;
    P.obs = (const float*)d_in[0];
    P.mem = (const float*)d_in[1];
    P.cw1 = (const float*)d_in[2];  P.cb1 = (const float*)d_in[3];
    P.cw2 = (const float*)d_in[4];  P.cb2 = (const float*)d_in[5];
    P.cw3 = (const float*)d_in[6];  P.cb3 = (const float*)d_in[7];
    for (int c = 0; c < 4; c++) {
        P.wih[c] = (const float*)d_in[8 + c * 4 + 0];
        P.whh[c] = (const float*)d_in[8 + c * 4 + 1];
        P.bih[c] = (const float*)d_in[8 + c * 4 + 2];
        P.bhh[c] = (const float*)d_in[8 + c * 4 + 3];
    }
    P.aw1 = (const float*)d_in[24]; P.ab1 = (const float*)d_in[25];
    P.aw2 = (const float*)d_in[26]; P.ab2 = (const float*)d_in[27];
    P.vw1 = (const float*)d_in[28]; P.vb1 = (const float*)d_in[29];
    P.vw2 = (const float*)d_in[30]; P.vb2 = (const float*)d_in[31];
    P.out = (float*)d_out;
    P.B   = in_sizes[0] / 147;   // obs elements = B*7*7*3

    cudaFuncSetAttribute(fused_kernel,
                         cudaFuncAttributeMaxDynamicSharedMemorySize, SMEM_BYTES);
    fused_kernel<<<P.B / TB, NT, SMEM_BYTES>>>(P);
}

// round 4
// speedup vs baseline: 1.0992x; 1.0000x over previous
#include <cuda_runtime.h>
#include <math.h>

// ---------------------------------------------------------------------------
// Fused GRU actor-critic forward, round 2: packed f32x2 FMA GEMMs,
// merged GRU gate pass, vectorized conv weight loads.
// One CTA (256 threads) owns a 128-sample tile entirely in shared memory.
// ---------------------------------------------------------------------------

#define NT   256           // threads per CTA
#define TB   128           // batch rows per CTA
#define AST  68            // activation row stride (64 + 4 pad, float4-able)
#define WST  196           // transposed-weight row stride (192 + 4 pad)
#define GHST 196           // gate buffer row stride

// smem arena (floats). Total 55552 floats = 222208 bytes.
#define O_ACT0  0          // [128][68]   activation ping
#define O_ACT1  8704       // [128][68]   activation pong
#define O_WT    17408      // [64][196]   transposed weight tile
#define O_BIAS  29952      // 512         biases / small head weights
#define O_GH    30464      // [128][196]  gate buffer
#define SMEM_FLOATS 55552
#define SMEM_BYTES  (SMEM_FLOATS * 4)

// conv-phase overlays (temporal reuse)
#define O_OBS   0          // [128][149]  staged obs (dead after conv1)
#define O_CW    19072      // 10544       conv weights+biases
#define O_PB    29616      // [128][145]  pooled conv1 output
#define O_Y2    0          // [128][132]  conv2 output (reuses obs region)
#define O_XT    29616      // [128][68]   conv3 output staging (PB dead)

typedef unsigned long long u64;

struct KParams {
    const float* obs;
    const float* mem;
    const float* cw1; const float* cb1;
    const float* cw2; const float* cb2;
    const float* cw3; const float* cb3;
    const float* wih[4]; const float* whh[4];
    const float* bih[4]; const float* bhh[4];
    const float* aw1; const float* ab1; const float* aw2; const float* ab2;
    const float* vw1; const float* vb1; const float* vw2; const float* vb2;
    float* out;
    int B;
};

__device__ __forceinline__ float sigf(float x) {
    return __fdividef(1.0f, 1.0f + __expf(-x));
}
__device__ __forceinline__ float tanh_fast(float x) {
    return 1.0f - __fdividef(2.0f, __expf(2.0f * x) + 1.0f);
}

// ---- packed f32x2 helpers -------------------------------------------------
__device__ __forceinline__ u64 splat2(float a) {
    u64 r; unsigned u = __float_as_uint(a);
    asm("mov.b64 %0, {%1, %1};" : "=l"(r) : "r"(u));
    return r;
}
__device__ __forceinline__ void ffma2(u64 &d, u64 a, u64 b) {
    asm("fma.rn.f32x2 %0, %1, %2, %0;" : "+l"(d) : "l"(a), "l"(b));
}
__device__ __forceinline__ float lo2(u64 v) { return __uint_as_float((unsigned)v); }
__device__ __forceinline__ float hi2(u64 v) { return __uint_as_float((unsigned)(v >> 32)); }

// Contiguous-column packed GEMM: thread computes rows [ty*8, ty*8+8) x
// column pairs [ubase, ubase+2*NP).  A smem [128][AST], WT smem [64][WST].
template<int NP>
__device__ __forceinline__ void gemmP(const float* __restrict__ A,
                                      const float* __restrict__ WT,
                                      const float* __restrict__ BIAS,
                                      int ty, int ubase, u64 (&acc)[8][NP])
{
#pragma unroll
    for (int j = 0; j < NP; j++) {
        u64 b0 = *reinterpret_cast<const u64*>(BIAS + ubase + 2 * j);
#pragma unroll
        for (int i = 0; i < 8; i++) acc[i][j] = b0;
    }
    const float* Ab = A + ty * 8 * AST;
#pragma unroll 2
    for (int k = 0; k < 64; k++) {
        u64 ap[8], bv[NP];
#pragma unroll
        for (int i = 0; i < 8; i++) ap[i] = splat2(Ab[i * AST + k]);
#pragma unroll
        for (int j = 0; j < NP; j++)
            bv[j] = *reinterpret_cast<const u64*>(WT + k * WST + ubase + 2 * j);
#pragma unroll
        for (int i = 0; i < 8; i++)
#pragma unroll
            for (int j = 0; j < NP; j++) ffma2(acc[i][j], ap[i], bv[j]);
    }
}

// Load 64 columns of the 256-wide memory matrix into an activation buffer.
__device__ __forceinline__ void load_h(float* dst, const float* mem,
                                       int r0, int off, int tid)
{
    for (int idx = tid; idx < TB * 16; idx += NT) {
        int m = idx >> 4, q = idx & 15;
        const float4 v = *reinterpret_cast<const float4*>(
            mem + (size_t)(r0 + m) * 256 + off + q * 4);
        *reinterpret_cast<float4*>(dst + m * AST + q * 4) = v;
    }
}

// One GRU cell.  AX = input x (read), AH = hidden h (read, overwritten with
// h').  h' also streamed to global memory_out (row stride 256).
__device__ void gru_cell(const float* AX, float* AH,
                         const float* __restrict__ wih, const float* __restrict__ whh,
                         const float* __restrict__ bih, const float* __restrict__ bhh,
                         float* WT, float* BIAS, float* GH,
                         float* __restrict__ moutg, int tid)
{
    // stage whh^T and biases
    for (int idx = tid; idx < 192 * 64; idx += NT) {
        int u = idx >> 6, k = idx & 63;
        WT[k * WST + u] = whh[idx];
    }
    for (int i = tid; i < 192; i += NT) { BIAS[i] = bih[i]; BIAS[192 + i] = bhh[i]; }
    __syncthreads();

    const int ty = tid >> 4, tx = tid & 15;

    // pass 1: gh = h @ whh^T + bhh  (all 192 columns, contiguous 12/thread)
    {
        u64 acc[8][6];
        gemmP<6>(AH, WT, BIAS + 192, ty, tx * 12, acc);
#pragma unroll
        for (int i = 0; i < 8; i++)
#pragma unroll
            for (int j = 0; j < 6; j++)
                *reinterpret_cast<u64*>(GH + (ty * 8 + i) * GHST + tx * 12 + 2 * j)
                    = acc[i][j];
    }
    __syncthreads();

    // stage wih^T
    for (int idx = tid; idx < 192 * 64; idx += NT) {
        int u = idx >> 6, k = idx & 63;
        WT[k * WST + u] = wih[idx];
    }
    __syncthreads();

    // pass 2: gi for gate-matched columns {ub, 64+ub, 128+ub} (4 each),
    // then fully thread-local gate combine.
    {
        const int ub = tx * 4;
        u64 acc[8][6];
#pragma unroll
        for (int g = 0; g < 3; g++)
#pragma unroll
        for (int p = 0; p < 2; p++) {
            u64 b0 = *reinterpret_cast<const u64*>(BIAS + g * 64 + ub + 2 * p);
#pragma unroll
            for (int i = 0; i < 8; i++) acc[i][g * 2 + p] = b0;
        }
        const float* Ab = AX + ty * 8 * AST;
#pragma unroll 2
        for (int k = 0; k < 64; k++) {
            u64 ap[8], bv[6];
#pragma unroll
            for (int i = 0; i < 8; i++) ap[i] = splat2(Ab[i * AST + k]);
#pragma unroll
            for (int g = 0; g < 3; g++)
#pragma unroll
            for (int p = 0; p < 2; p++)
                bv[g * 2 + p] = *reinterpret_cast<const u64*>(
                    WT + k * WST + g * 64 + ub + 2 * p);
#pragma unroll
            for (int i = 0; i < 8; i++)
#pragma unroll
                for (int j = 0; j < 6; j++) ffma2(acc[i][j], ap[i], bv[j]);
        }
#pragma unroll
        for (int i = 0; i < 8; i++) {
            const int m = ty * 8 + i;
            const float4 ghr = *reinterpret_cast<const float4*>(GH + m * GHST + ub);
            const float4 ghz = *reinterpret_cast<const float4*>(GH + m * GHST + 64 + ub);
            const float4 ghn = *reinterpret_cast<const float4*>(GH + m * GHST + 128 + ub);
            const float4 h4  = *reinterpret_cast<const float4*>(AH + m * AST + ub);
            float gr[4] = { lo2(acc[i][0]), hi2(acc[i][0]), lo2(acc[i][1]), hi2(acc[i][1]) };
            float gz[4] = { lo2(acc[i][2]), hi2(acc[i][2]), lo2(acc[i][3]), hi2(acc[i][3]) };
            float gn[4] = { lo2(acc[i][4]), hi2(acc[i][4]), lo2(acc[i][5]), hi2(acc[i][5]) };
            const float hr[4] = { ghr.x, ghr.y, ghr.z, ghr.w };
            const float hz[4] = { ghz.x, ghz.y, ghz.z, ghz.w };
            const float hn[4] = { ghn.x, ghn.y, ghn.z, ghn.w };
            const float ho[4] = { h4.x, h4.y, h4.z, h4.w };
            float hp[4];
#pragma unroll
            for (int c = 0; c < 4; c++) {
                float r = sigf(gr[c] + hr[c]);
                float z = sigf(gz[c] + hz[c]);
                float n = tanh_fast(gn[c] + r * hn[c]);
                hp[c] = n + z * (ho[c] - n);
            }
            const float4 o4 = make_float4(hp[0], hp[1], hp[2], hp[3]);
            *reinterpret_cast<float4*>(AH + m * AST + ub) = o4;
            *reinterpret_cast<float4*>(moutg + (size_t)m * 256 + ub) = o4;
        }
    }
    __syncthreads();
}

__global__ void __launch_bounds__(NT, 1) fused_kernel(KParams P)
{
    extern __shared__ float S[];
    const int tid = threadIdx.x;
    const int r0  = blockIdx.x * TB;
    const int B   = P.B;

    // =================== conv phase ===================
    float* OBSB = S + O_OBS;
    float* CW   = S + O_CW;
    float* PB   = S + O_PB;
    float* Y2   = S + O_Y2;
    float* XT   = S + O_XT;

    // stage conv weights: w1[0:192) b1[192:208) w2[208:2256) b2[2256:2288)
    //                     w3[2288:10480) b3[10480:10544)
    for (int i = tid; i < 192;  i += NT) CW[i]         = P.cw1[i];
    for (int i = tid; i < 16;   i += NT) CW[192 + i]   = P.cb1[i];
    for (int i = tid; i < 2048; i += NT) CW[208 + i]   = P.cw2[i];
    for (int i = tid; i < 32;   i += NT) CW[2256 + i]  = P.cb2[i];
    for (int i = tid; i < 8192; i += NT) CW[2288 + i]  = P.cw3[i];
    for (int i = tid; i < 64;   i += NT) CW[10480 + i] = P.cb3[i];

    // stage obs tile (NHWC, 147 floats / sample, padded row stride 149)
    for (int idx = tid; idx < TB * 147; idx += NT) {
        int m = idx / 147, e = idx - m * 147;
        OBSB[m * 149 + e] = P.obs[(size_t)(r0 + m) * 147 + e];
    }
    __syncthreads();

    const int s = tid & 127, half = tid >> 7;   // 2 threads per sample

    // conv1 (3->16ch, 2x2) + relu + 2x2 maxpool
    {
        const float* ob = OBSB + s * 149;
        float w1r[8][12], b1r[8];
#pragma unroll
        for (int c = 0; c < 8; c++) {
            b1r[c] = CW[192 + half * 8 + c];
#pragma unroll
            for (int q = 0; q < 12; q++) w1r[c][q] = CW[(half * 8 + c) * 12 + q];
        }
#pragma unroll
        for (int a = 0; a < 3; a++)
#pragma unroll
        for (int b = 0; b < 3; b++) {
            float vmax[8];
#pragma unroll
            for (int c = 0; c < 8; c++) vmax[c] = -1e30f;
#pragma unroll
            for (int di = 0; di < 2; di++)
#pragma unroll
            for (int dj = 0; dj < 2; dj++) {
                int i = 2 * a + di, j = 2 * b + dj;
                float o[12];
#pragma unroll
                for (int kh = 0; kh < 2; kh++)
#pragma unroll
                for (int kw = 0; kw < 2; kw++)
#pragma unroll
                for (int c3 = 0; c3 < 3; c3++)
                    o[c3 * 4 + kh * 2 + kw] = ob[(i + kh) * 21 + (j + kw) * 3 + c3];
#pragma unroll
                for (int c = 0; c < 8; c++) {
                    float v = b1r[c];
#pragma unroll
                    for (int q = 0; q < 12; q++) v = fmaf(o[q], w1r[c][q], v);
                    vmax[c] = fmaxf(vmax[c], v);
                }
            }
#pragma unroll
            for (int c = 0; c < 8; c++)
                PB[s * 145 + (half * 8 + c) * 9 + a * 3 + b] = fmaxf(vmax[c], 0.0f);
        }
    }
    __syncthreads();

    // conv2 (16->32ch, 2x2 on 3x3 -> 2x2) + relu, float4 weight loads
    {
#pragma unroll
        for (int pi = 0; pi < 2; pi++)
#pragma unroll
        for (int pj = 0; pj < 2; pj++) {
            float pv[64];
#pragma unroll
            for (int c1 = 0; c1 < 16; c1++)
#pragma unroll
            for (int kh = 0; kh < 2; kh++)
#pragma unroll
            for (int kw = 0; kw < 2; kw++)
                pv[c1 * 4 + kh * 2 + kw] =
                    PB[s * 145 + c1 * 9 + (pi + kh) * 3 + (pj + kw)];
            for (int c2l = 0; c2l < 16; c2l++) {
                int c2 = half * 16 + c2l;
                float v = CW[2256 + c2];
                const float4* w4 = reinterpret_cast<const float4*>(CW + 208 + c2 * 64);
#pragma unroll
                for (int t = 0; t < 16; t++) {
                    float4 w = w4[t];
                    v = fmaf(pv[4 * t + 0], w.x, v);
                    v = fmaf(pv[4 * t + 1], w.y, v);
                    v = fmaf(pv[4 * t + 2], w.z, v);
                    v = fmaf(pv[4 * t + 3], w.w, v);
                }
                Y2[s * 132 + c2 * 4 + pi * 2 + pj] = fmaxf(v, 0.0f);
            }
        }
    }
    __syncthreads();

    // conv3 (32->64ch, 2x2 on 2x2 -> 1x1) + relu, float4 loads both sides
    {
        float acc3[32];
#pragma unroll
        for (int o = 0; o < 32; o++) acc3[o] = CW[10480 + half * 32 + o];
#pragma unroll
        for (int ch = 0; ch < 4; ch++) {
            float4 yv4[8];
#pragma unroll
            for (int q = 0; q < 8; q++)
                yv4[q] = *reinterpret_cast<const float4*>(Y2 + s * 132 + ch * 32 + q * 4);
            for (int o = 0; o < 32; o++) {
                const float4* w4 = reinterpret_cast<const float4*>(
                    CW + 2288 + (half * 32 + o) * 128 + ch * 32);
                float v = acc3[o];
#pragma unroll
                for (int q = 0; q < 8; q++) {
                    float4 w = w4[q];
                    v = fmaf(yv4[q].x, w.x, v);
                    v = fmaf(yv4[q].y, w.y, v);
                    v = fmaf(yv4[q].z, w.z, v);
                    v = fmaf(yv4[q].w, w.w, v);
                }
                acc3[o] = v;
            }
        }
#pragma unroll
        for (int o = 0; o < 32; o++)
            XT[s * AST + half * 32 + o] = fmaxf(acc3[o], 0.0f);
    }
    __syncthreads();

    // =================== GRU phase ===================
    float* A0   = S + O_ACT0;
    float* A1   = S + O_ACT1;
    float* WT   = S + O_WT;
    float* BIAS = S + O_BIAS;
    float* GH   = S + O_GH;

    // move conv output into ACT0 (XT overlaps BIAS/GH region)
    for (int i = tid; i < TB * AST / 4; i += NT)
        reinterpret_cast<float4*>(A0)[i] = reinterpret_cast<const float4*>(XT)[i];
    __syncthreads();

    float* moutg = P.out + (size_t)4 * B + (size_t)r0 * 256;

    load_h(A1, P.mem, r0, 0, tid);
    __syncthreads();
    gru_cell(A0, A1, P.wih[0], P.whh[0], P.bih[0], P.bhh[0],
             WT, BIAS, GH, moutg + 0, tid);          // h1_0 -> A1

    load_h(A0, P.mem, r0, 64, tid);
    __syncthreads();
    gru_cell(A1, A0, P.wih[1], P.whh[1], P.bih[1], P.bhh[1],
             WT, BIAS, GH, moutg + 64, tid);         // h1_1 -> A0

    load_h(A1, P.mem, r0, 128, tid);
    __syncthreads();
    gru_cell(A0, A1, P.wih[2], P.whh[2], P.bih[2], P.bhh[2],
             WT, BIAS, GH, moutg + 128, tid);        // h2_0 -> A1

    load_h(A0, P.mem, r0, 192, tid);
    __syncthreads();
    gru_cell(A1, A0, P.wih[3], P.whh[3], P.bih[3], P.bhh[3],
             WT, BIAS, GH, moutg + 192, tid);        // h2_1 (embedding) -> A0

    // =================== heads ===================
    // stack actor_w1 (cols 0..63) and critic_w1 (cols 64..127) -> one GEMM
    for (int idx = tid; idx < 64 * 64; idx += NT) {
        int u = idx >> 6, k = idx & 63;
        WT[k * WST + u] = P.aw1[idx];
    }
    for (int idx = tid; idx < 64 * 64; idx += NT) {
        int u = idx >> 6, k = idx & 63;
        WT[k * WST + 64 + u] = P.vw1[idx];
    }
    for (int i = tid; i < 64; i += NT) { BIAS[i] = P.ab1[i]; BIAS[64 + i] = P.vb1[i]; }
    for (int i = tid; i < 192; i += NT) BIAS[128 + i] = P.aw2[i];
    for (int i = tid; i < 3;   i += NT) BIAS[320 + i] = P.ab2[i];
    for (int i = tid; i < 64;  i += NT) BIAS[336 + i] = P.vw2[i];
    if (tid == 0) BIAS[400] = P.vb2[0];
    __syncthreads();

    {
        const int ty = tid >> 4, tx = tid & 15;
        u64 acc[8][4];
        gemmP<4>(A0, WT, BIAS, ty, tx * 8, acc);
#pragma unroll
        for (int i = 0; i < 8; i++) {
            float* g = GH + (ty * 8 + i) * 132 + tx * 8;
#pragma unroll
            for (int j = 0; j < 4; j++) {
                g[2 * j + 0] = fmaxf(lo2(acc[i][j]), 0.0f);
                g[2 * j + 1] = fmaxf(hi2(acc[i][j]), 0.0f);
            }
        }
    }
    __syncthreads();

    if (tid < 128) {
        // actor second layer + log_softmax for sample m
        const int m = tid;
        float l0 = BIAS[320], l1 = BIAS[321], l2 = BIAS[322];
        for (int k = 0; k < 64; k++) {
            float a = GH[m * 132 + k];
            l0 = fmaf(a, BIAS[128 + k],       l0);
            l1 = fmaf(a, BIAS[128 + 64 + k],  l1);
            l2 = fmaf(a, BIAS[128 + 128 + k], l2);
        }
        float mx  = fmaxf(l0, fmaxf(l1, l2));
        float lse = mx + logf(__expf(l0 - mx) + __expf(l1 - mx) + __expf(l2 - mx));
        float* o = P.out + (size_t)(r0 + m) * 3;
        o[0] = l0 - lse; o[1] = l1 - lse; o[2] = l2 - lse;
    } else {
        // critic second layer for sample m
        const int m = tid - 128;
        float v = BIAS[400];
        for (int k = 0; k < 64; k++)
            v = fmaf(GH[m * 132 + 64 + k], BIAS[336 + k], v);
        P.out[(size_t)3 * B + r0 + m] = v;
    }
}

extern "C" void kernel_launch(void* const* d_in, const int* in_sizes, int n_in,
                              void* d_out, int out_size)
{
    KParams P;
    P.obs = (const float*)d_in[0];
    P.mem = (const float*)d_in[1];
    P.cw1 = (const float*)d_in[2];  P.cb1 = (const float*)d_in[3];
    P.cw2 = (const float*)d_in[4];  P.cb2 = (const float*)d_in[5];
    P.cw3 = (const float*)d_in[6];  P.cb3 = (const float*)d_in[7];
    for (int c = 0; c < 4; c++) {
        P.wih[c] = (const float*)d_in[8 + c * 4 + 0];
        P.whh[c] = (const float*)d_in[8 + c * 4 + 1];
        P.bih[c] = (const float*)d_in[8 + c * 4 + 2];
        P.bhh[c] = (const float*)d_in[8 + c * 4 + 3];
    }
    P.aw1 = (const float*)d_in[24]; P.ab1 = (const float*)d_in[25];
    P.aw2 = (const float*)d_in[26]; P.ab2 = (const float*)d_in[27];
    P.vw1 = (const float*)d_in[28]; P.vb1 = (const float*)d_in[29];
    P.vw2 = (const float*)d_in[30]; P.vb2 = (const float*)d_in[31];
    P.out = (float*)d_out;
    P.B   = in_sizes[0] / 147;   // obs elements = B*7*7*3

    cudaFuncSetAttribute(fused_kernel,
                         cudaFuncAttributeMaxDynamicSharedMemorySize, SMEM_BYTES);
    fused_kernel<<<P.B / TB, NT, SMEM_BYTES>>>(P);
}